// round 10
// baseline (speedup 1.0000x reference)
#include <cuda_runtime.h>
#include <cstdint>

#define N_NODES 50000
#define N_EDGES 800000
#define D 256
#define BN_EPS 1e-5f
#define SCAN_NB 196            // ceil(50000/256)

typedef unsigned long long u64;

// ---------------- scratch (device globals: allocation-free) ----------------
__device__ int   g_cnt[N_NODES];        // in-degree (without self loop)
__device__ int   g_fill[N_NODES];       // CSR fill cursors
__device__ int   g_off[N_NODES];        // CSR offsets (exclusive scan of cnt)
__device__ int   g_csr_src[N_EDGES];    // edge sources grouped by destination
__device__ float g_dinv[N_NODES];
__device__ int   g_part[256];           // per-block partial sums (scan)
__device__ int   g_partpref[256];       // exclusive prefix of partials
__device__ float g_hprime[(size_t)N_NODES * D];   // dinv[i] * (x[i] @ W^T)
__device__ float g_agg[(size_t)N_NODES * D];      // aggregated (+bias) result
__device__ float g_sum[D];
__device__ float g_sumsq[D];
__device__ float g_scale[D];
__device__ float g_shift[D];

// ---------------- 1) init counters + BN sums ----------------
__global__ void init_kernel() {
    int i = blockIdx.x * blockDim.x + threadIdx.x;
    if (i < N_NODES) { g_cnt[i] = 0; g_fill[i] = 0; }
    if (i < D) { g_sum[i] = 0.0f; g_sumsq[i] = 0.0f; }
}

// ---------------- 2) in-degree count over edge targets (int32 indices) ----
__global__ void count_kernel(const int* __restrict__ col) {
    int e = blockIdx.x * blockDim.x + threadIdx.x;
    if (e < N_EDGES) atomicAdd(&g_cnt[col[e]], 1);
}

// ---------------- 3a) per-block sums of cnt ----------------
__global__ void __launch_bounds__(256) blocksum_kernel() {
    const int tid  = threadIdx.x;
    const int lane = tid & 31;
    const int wid  = tid >> 5;
    int i = blockIdx.x * 256 + tid;
    int v = (i < N_NODES) ? g_cnt[i] : 0;
#pragma unroll
    for (int ofs = 16; ofs > 0; ofs >>= 1)
        v += __shfl_down_sync(0xffffffffu, v, ofs);
    __shared__ int ws[8];
    if (lane == 0) ws[wid] = v;
    __syncthreads();
    if (tid == 0) {
        int s = 0;
#pragma unroll
        for (int w = 0; w < 8; w++) s += ws[w];
        g_part[blockIdx.x] = s;
    }
}

// ---------------- 3b) exclusive scan of 196 partials (1 block) ------------
__global__ void __launch_bounds__(256) partscan_kernel() {
    __shared__ int sm[256];
    const int tid = threadIdx.x;
    int v = (tid < SCAN_NB) ? g_part[tid] : 0;
    sm[tid] = v;
    __syncthreads();
#pragma unroll
    for (int ofs = 1; ofs < 256; ofs <<= 1) {
        int t = (tid >= ofs) ? sm[tid - ofs] : 0;
        __syncthreads();
        sm[tid] += t;
        __syncthreads();
    }
    if (tid < SCAN_NB) g_partpref[tid] = sm[tid] - v;   // exclusive
}

// ---------------- 3c) per-block exclusive scan + prefix, and dinv ---------
__global__ void __launch_bounds__(256) offsets_kernel() {
    __shared__ int sm[256];
    const int tid = threadIdx.x;
    int i = blockIdx.x * 256 + tid;
    int v = (i < N_NODES) ? g_cnt[i] : 0;
    sm[tid] = v;
    __syncthreads();
#pragma unroll
    for (int ofs = 1; ofs < 256; ofs <<= 1) {
        int t = (tid >= ofs) ? sm[tid - ofs] : 0;
        __syncthreads();
        sm[tid] += t;
        __syncthreads();
    }
    if (i < N_NODES) {
        g_off[i]  = sm[tid] - v + g_partpref[blockIdx.x];
        g_dinv[i] = rsqrtf((float)(v + 1));
    }
}

// ---------------- 4) fill CSR: group edge sources by destination ----------
__global__ void fill_kernel(const int* __restrict__ row,
                            const int* __restrict__ col) {
    int e = blockIdx.x * blockDim.x + threadIdx.x;
    if (e >= N_EDGES) return;
    int src = row[e];
    int dst = col[e];
    int pos = g_off[dst] + atomicAdd(&g_fill[dst], 1);
    g_csr_src[pos] = src;
}

// ---------------- packed-f32x2 helpers ----------------
__device__ __forceinline__ u64 pack_dup(float a) {
    u64 r;
    unsigned int ai = __float_as_uint(a);
    asm("mov.b64 %0, {%1, %2};" : "=l"(r) : "r"(ai), "r"(ai));
    return r;
}
__device__ __forceinline__ void fma2(u64& acc, u64 a, u64 b) {
    asm("fma.rn.f32x2 %0, %1, %2, %0;" : "+l"(acc) : "l"(a), "l"(b));
}

// ---------------- 5) SGEMM h' = dinv .* (x @ W^T), f32x2 FMA --------------
// BM=128, BN=128, BK=8, TM=8, TN=8 (packed as 4 pairs), 256 threads.
__global__ void __launch_bounds__(256) gemm_kernel(const float* __restrict__ x,
                                                   const float* __restrict__ W) {
    __shared__ float As[2][8][128];
    __shared__ float Bs[2][8][128];
    const int brow = blockIdx.x * 128;
    const int bcol = blockIdx.y * 128;
    const int tid  = threadIdx.x;
    const int tx   = tid & 15;
    const int ty   = tid >> 4;
    const int lrow = tid >> 1;          // 0..127
    const int lcol = (tid & 1) * 4;     // 0 or 4

    u64 acc2[8][4];                     // [i][jp] = cols (2jp, 2jp+1)
#pragma unroll
    for (int i = 0; i < 8; i++)
#pragma unroll
        for (int j = 0; j < 4; j++) acc2[i][j] = 0ULL;

    const int  arow   = brow + lrow;
    const bool avalid = (arow < N_NODES);
    const float* xa = x + (size_t)arow * D + lcol;
    const float* wb = W + (size_t)(bcol + lrow) * D + lcol;

    // preload k0 = 0 into buffer 0
    {
        float4 av = avalid ? *reinterpret_cast<const float4*>(xa)
                           : make_float4(0.f, 0.f, 0.f, 0.f);
        float4 bv = *reinterpret_cast<const float4*>(wb);
        As[0][lcol + 0][lrow] = av.x; As[0][lcol + 1][lrow] = av.y;
        As[0][lcol + 2][lrow] = av.z; As[0][lcol + 3][lrow] = av.w;
        Bs[0][lcol + 0][lrow] = bv.x; Bs[0][lcol + 1][lrow] = bv.y;
        Bs[0][lcol + 2][lrow] = bv.z; Bs[0][lcol + 3][lrow] = bv.w;
    }
    __syncthreads();

    int buf = 0;
    for (int k0 = 0; k0 < D; k0 += 8) {
        float4 nav, nbv;
        const bool more = (k0 + 8 < D);
        if (more) {
            nav = avalid ? *reinterpret_cast<const float4*>(xa + k0 + 8)
                         : make_float4(0.f, 0.f, 0.f, 0.f);
            nbv = *reinterpret_cast<const float4*>(wb + k0 + 8);
        }
#pragma unroll
        for (int k = 0; k < 8; k++) {
            float4 a0 = *reinterpret_cast<const float4*>(&As[buf][k][ty * 8]);
            float4 a1 = *reinterpret_cast<const float4*>(&As[buf][k][ty * 8 + 4]);
            ulonglong2 bq0 = *reinterpret_cast<const ulonglong2*>(&Bs[buf][k][tx * 8]);
            ulonglong2 bq1 = *reinterpret_cast<const ulonglong2*>(&Bs[buf][k][tx * 8 + 4]);
            u64 b2[4] = {bq0.x, bq0.y, bq1.x, bq1.y};
            u64 ad[8];
            ad[0] = pack_dup(a0.x); ad[1] = pack_dup(a0.y);
            ad[2] = pack_dup(a0.z); ad[3] = pack_dup(a0.w);
            ad[4] = pack_dup(a1.x); ad[5] = pack_dup(a1.y);
            ad[6] = pack_dup(a1.z); ad[7] = pack_dup(a1.w);
#pragma unroll
            for (int i = 0; i < 8; i++)
#pragma unroll
                for (int j = 0; j < 4; j++)
                    fma2(acc2[i][j], ad[i], b2[j]);
        }
        if (more) {
            int nb = buf ^ 1;
            As[nb][lcol + 0][lrow] = nav.x; As[nb][lcol + 1][lrow] = nav.y;
            As[nb][lcol + 2][lrow] = nav.z; As[nb][lcol + 3][lrow] = nav.w;
            Bs[nb][lcol + 0][lrow] = nbv.x; Bs[nb][lcol + 1][lrow] = nbv.y;
            Bs[nb][lcol + 2][lrow] = nbv.z; Bs[nb][lcol + 3][lrow] = nbv.w;
            __syncthreads();
            buf = nb;
        }
    }

#pragma unroll
    for (int i = 0; i < 8; i++) {
        int gr = brow + ty * 8 + i;
        if (gr >= N_NODES) continue;
        float  dv   = g_dinv[gr];
        size_t base = (size_t)gr * D + bcol + tx * 8;
        float2 p0 = *reinterpret_cast<float2*>(&acc2[i][0]);
        float2 p1 = *reinterpret_cast<float2*>(&acc2[i][1]);
        float2 p2 = *reinterpret_cast<float2*>(&acc2[i][2]);
        float2 p3 = *reinterpret_cast<float2*>(&acc2[i][3]);
        float4 v0 = make_float4(p0.x * dv, p0.y * dv, p1.x * dv, p1.y * dv);
        float4 v1 = make_float4(p2.x * dv, p2.y * dv, p3.x * dv, p3.y * dv);
        *reinterpret_cast<float4*>(g_hprime + base)     = v0;
        *reinterpret_cast<float4*>(g_hprime + base + 4) = v1;
    }
}

// ---------------- 6) gather-aggregate + fused BN column stats -------------
// agg[c] = dinv[c] * ( h'[c] + sum_{src in N(c)} h'[src] ) + bias
__device__ __forceinline__ void acc4(float4& a, const float4& b) {
    a.x += b.x; a.y += b.y; a.z += b.z; a.w += b.w;
}

__global__ void __launch_bounds__(256) aggregate_kernel(const float* __restrict__ bias) {
    __shared__ float s_sum[D];
    __shared__ float s_sq[D];
    const int tid  = threadIdx.x;
    const int lane = tid & 31;
    const int wid  = tid >> 5;
    s_sum[tid] = 0.0f;
    s_sq[tid]  = 0.0f;
    __syncthreads();

    const float4* hp4 = reinterpret_cast<const float4*>(g_hprime);
    float4*       out4 = reinterpret_cast<float4*>(g_agg);
    const float4* b4   = reinterpret_cast<const float4*>(bias);
    const float4 bb0 = b4[lane];
    const float4 bb1 = b4[lane + 32];

    float4 ts0 = make_float4(0.f, 0.f, 0.f, 0.f);   // sums, cols 4*lane..+3
    float4 ts1 = make_float4(0.f, 0.f, 0.f, 0.f);   // sums, cols 128+4*lane..+3
    float4 tq0 = make_float4(0.f, 0.f, 0.f, 0.f);   // sumsq
    float4 tq1 = make_float4(0.f, 0.f, 0.f, 0.f);

    const int warp0  = blockIdx.x * 8 + wid;
    const int nwarps = gridDim.x * 8;

    for (int c = warp0; c < N_NODES; c += nwarps) {
        // self-loop contribution
        float4 a0 = hp4[(size_t)c * 64 + lane];
        float4 a1 = hp4[(size_t)c * 64 + lane + 32];
        float4 e0 = make_float4(0.f, 0.f, 0.f, 0.f);
        float4 e1 = make_float4(0.f, 0.f, 0.f, 0.f);

        const int beg = g_off[c];
        const int end = beg + g_cnt[c];
        int e = beg;
        for (; e + 1 < end; e += 2) {
            int s0 = g_csr_src[e];
            int s1 = g_csr_src[e + 1];
            const float4* p0 = hp4 + (size_t)s0 * 64;
            const float4* p1 = hp4 + (size_t)s1 * 64;
            float4 u0 = p0[lane], u1 = p0[lane + 32];
            float4 w0 = p1[lane], w1 = p1[lane + 32];
            acc4(a0, u0); acc4(a1, u1);
            acc4(e0, w0); acc4(e1, w1);
        }
        if (e < end) {
            int s0 = g_csr_src[e];
            const float4* p0 = hp4 + (size_t)s0 * 64;
            acc4(a0, p0[lane]); acc4(a1, p0[lane + 32]);
        }
        acc4(a0, e0); acc4(a1, e1);

        const float dv = g_dinv[c];
        a0.x = fmaf(a0.x, dv, bb0.x); a0.y = fmaf(a0.y, dv, bb0.y);
        a0.z = fmaf(a0.z, dv, bb0.z); a0.w = fmaf(a0.w, dv, bb0.w);
        a1.x = fmaf(a1.x, dv, bb1.x); a1.y = fmaf(a1.y, dv, bb1.y);
        a1.z = fmaf(a1.z, dv, bb1.z); a1.w = fmaf(a1.w, dv, bb1.w);

        out4[(size_t)c * 64 + lane]      = a0;
        out4[(size_t)c * 64 + lane + 32] = a1;

        acc4(ts0, a0); acc4(ts1, a1);
        tq0.x = fmaf(a0.x, a0.x, tq0.x); tq0.y = fmaf(a0.y, a0.y, tq0.y);
        tq0.z = fmaf(a0.z, a0.z, tq0.z); tq0.w = fmaf(a0.w, a0.w, tq0.w);
        tq1.x = fmaf(a1.x, a1.x, tq1.x); tq1.y = fmaf(a1.y, a1.y, tq1.y);
        tq1.z = fmaf(a1.z, a1.z, tq1.z); tq1.w = fmaf(a1.w, a1.w, tq1.w);
    }

    // block-level reduce into shared
    const int c0 = 4 * lane;
    atomicAdd(&s_sum[c0 + 0], ts0.x); atomicAdd(&s_sum[c0 + 1], ts0.y);
    atomicAdd(&s_sum[c0 + 2], ts0.z); atomicAdd(&s_sum[c0 + 3], ts0.w);
    atomicAdd(&s_sum[128 + c0 + 0], ts1.x); atomicAdd(&s_sum[128 + c0 + 1], ts1.y);
    atomicAdd(&s_sum[128 + c0 + 2], ts1.z); atomicAdd(&s_sum[128 + c0 + 3], ts1.w);
    atomicAdd(&s_sq[c0 + 0], tq0.x); atomicAdd(&s_sq[c0 + 1], tq0.y);
    atomicAdd(&s_sq[c0 + 2], tq0.z); atomicAdd(&s_sq[c0 + 3], tq0.w);
    atomicAdd(&s_sq[128 + c0 + 0], tq1.x); atomicAdd(&s_sq[128 + c0 + 1], tq1.y);
    atomicAdd(&s_sq[128 + c0 + 2], tq1.z); atomicAdd(&s_sq[128 + c0 + 3], tq1.w);
    __syncthreads();

    atomicAdd(&g_sum[tid],   s_sum[tid]);
    atomicAdd(&g_sumsq[tid], s_sq[tid]);
}

// ---------------- 7) BN affine params ----------
__global__ void bn_params_kernel(const float* __restrict__ gamma,
                                 const float* __restrict__ beta) {
    int t = threadIdx.x;
    float invN = 1.0f / (float)N_NODES;
    float mean = g_sum[t] * invN;
    float var  = g_sumsq[t] * invN - mean * mean;
    float sc   = gamma[t] * rsqrtf(var + BN_EPS);
    g_scale[t] = sc;
    g_shift[t] = beta[t] - mean * sc;
}

// ---------------- 8) y = relu(agg*scale + shift) ----------
__global__ void output_kernel(float* __restrict__ out) {
    int i = blockIdx.x * blockDim.x + threadIdx.x;       // float4 index
    const int total4 = N_NODES * D / 4;
    if (i >= total4) return;
    int c = (i & 63) * 4;
    float4 v  = reinterpret_cast<const float4*>(g_agg)[i];
    float4 sc = *reinterpret_cast<const float4*>(g_scale + c);
    float4 sh = *reinterpret_cast<const float4*>(g_shift + c);
    float4 y;
    y.x = fmaxf(fmaf(v.x, sc.x, sh.x), 0.0f);
    y.y = fmaxf(fmaf(v.y, sc.y, sh.y), 0.0f);
    y.z = fmaxf(fmaf(v.z, sc.z, sh.z), 0.0f);
    y.w = fmaxf(fmaf(v.w, sc.w, sh.w), 0.0f);
    reinterpret_cast<float4*>(out)[i] = y;
}

// ---------------- launch ----------------
extern "C" void kernel_launch(void* const* d_in, const int* in_sizes, int n_in,
                              void* d_out, int out_size) {
    const float* x     = (const float*)d_in[0];
    const int*   ei    = (const int*)d_in[1];     // int32 (JAX x64 disabled)
    const float* W     = (const float*)d_in[2];
    const float* bias  = (const float*)d_in[3];
    const float* gamma = (const float*)d_in[4];
    const float* beta  = (const float*)d_in[5];
    const int*   row   = ei;              // sources
    const int*   col   = ei + N_EDGES;    // targets
    float* out = (float*)d_out;

    init_kernel<<<(N_NODES + 255) / 256, 256>>>();
    count_kernel<<<(N_EDGES + 255) / 256, 256>>>(col);
    blocksum_kernel<<<SCAN_NB, 256>>>();
    partscan_kernel<<<1, 256>>>();
    offsets_kernel<<<SCAN_NB, 256>>>();
    fill_kernel<<<(N_EDGES + 255) / 256, 256>>>(row, col);

    dim3 gemm_grid((N_NODES + 127) / 128, D / 128);
    gemm_kernel<<<gemm_grid, 256>>>(x, W);

    aggregate_kernel<<<592, 256>>>(bias);

    bn_params_kernel<<<1, 256>>>(gamma, beta);
    output_kernel<<<(N_NODES * D / 4 + 255) / 256, 256>>>(out);
}

// round 11
// speedup vs baseline: 1.9427x; 1.9427x over previous
#include <cuda_runtime.h>
#include <cuda_bf16.h>
#include <cstdint>

#define N_NODES 50000
#define N_EDGES 800000
#define D 256
#define BN_EPS 1e-5f
#define SCAN_NB 196            // ceil(50000/256)

// ---------------- scratch (device globals: allocation-free) ----------------
__device__ int   g_cnt[N_NODES];        // in-degree (without self loop)
__device__ int   g_fill[N_NODES];       // CSR fill cursors
__device__ int   g_off[N_NODES];        // CSR offsets (exclusive scan of cnt)
__device__ int   g_csr_src[N_EDGES];    // edge sources grouped by destination
__device__ float g_dinv[N_NODES];
__device__ int   g_part[256];           // per-block partial sums (scan)
__device__ int   g_partpref[256];       // exclusive prefix of partials
__device__ float g_hprime[(size_t)N_NODES * D];   // dinv[i] * (x[i] @ W^T)
__device__ float g_agg[(size_t)N_NODES * D];      // aggregated (+bias) result
__device__ float g_sum[D];
__device__ float g_sumsq[D];
__device__ float g_scale[D];
__device__ float g_shift[D];

// ---------------- 1) init counters + BN sums ----------------
__global__ void init_kernel() {
    int i = blockIdx.x * blockDim.x + threadIdx.x;
    if (i < N_NODES) { g_cnt[i] = 0; g_fill[i] = 0; }
    if (i < D) { g_sum[i] = 0.0f; g_sumsq[i] = 0.0f; }
}

// ---------------- 2) in-degree count over edge targets (int32 indices) ----
__global__ void count_kernel(const int* __restrict__ col) {
    int e = blockIdx.x * blockDim.x + threadIdx.x;
    if (e < N_EDGES) atomicAdd(&g_cnt[col[e]], 1);
}

// ---------------- 3a) per-block sums of cnt ----------------
__global__ void __launch_bounds__(256) blocksum_kernel() {
    const int tid  = threadIdx.x;
    const int lane = tid & 31;
    const int wid  = tid >> 5;
    int i = blockIdx.x * 256 + tid;
    int v = (i < N_NODES) ? g_cnt[i] : 0;
#pragma unroll
    for (int ofs = 16; ofs > 0; ofs >>= 1)
        v += __shfl_down_sync(0xffffffffu, v, ofs);
    __shared__ int ws[8];
    if (lane == 0) ws[wid] = v;
    __syncthreads();
    if (tid == 0) {
        int s = 0;
#pragma unroll
        for (int w = 0; w < 8; w++) s += ws[w];
        g_part[blockIdx.x] = s;
    }
}

// ---------------- 3b) exclusive scan of 196 partials (1 block) ------------
__global__ void __launch_bounds__(256) partscan_kernel() {
    __shared__ int sm[256];
    const int tid = threadIdx.x;
    int v = (tid < SCAN_NB) ? g_part[tid] : 0;
    sm[tid] = v;
    __syncthreads();
#pragma unroll
    for (int ofs = 1; ofs < 256; ofs <<= 1) {
        int t = (tid >= ofs) ? sm[tid - ofs] : 0;
        __syncthreads();
        sm[tid] += t;
        __syncthreads();
    }
    if (tid < SCAN_NB) g_partpref[tid] = sm[tid] - v;   // exclusive
}

// ---------------- 3c) per-block exclusive scan + prefix, and dinv ---------
__global__ void __launch_bounds__(256) offsets_kernel() {
    __shared__ int sm[256];
    const int tid = threadIdx.x;
    int i = blockIdx.x * 256 + tid;
    int v = (i < N_NODES) ? g_cnt[i] : 0;
    sm[tid] = v;
    __syncthreads();
#pragma unroll
    for (int ofs = 1; ofs < 256; ofs <<= 1) {
        int t = (tid >= ofs) ? sm[tid - ofs] : 0;
        __syncthreads();
        sm[tid] += t;
        __syncthreads();
    }
    if (i < N_NODES) {
        g_off[i]  = sm[tid] - v + g_partpref[blockIdx.x];
        g_dinv[i] = rsqrtf((float)(v + 1));
    }
}

// ---------------- 4) fill CSR: group edge sources by destination ----------
__global__ void fill_kernel(const int* __restrict__ row,
                            const int* __restrict__ col) {
    int e = blockIdx.x * blockDim.x + threadIdx.x;
    if (e >= N_EDGES) return;
    int src = row[e];
    int dst = col[e];
    int pos = g_off[dst] + atomicAdd(&g_fill[dst], 1);
    g_csr_src[pos] = src;
}

// ---------------- 5) tensor-core GEMM: h' = dinv .* (x @ W^T) -------------
// 3xBF16 split on mma.sync.m16n8k16. BM=128, BN=64, BK=32.
// 8 warps: warp_m = wid&1 (2), warp_n = wid>>1 (4). Warp tile 64x16.
#define APAD 40   // bf16 row stride (32 data + 8 pad) -> conflict-free quads

__device__ __forceinline__ void bf16_split(float v, __nv_bfloat16& hi, __nv_bfloat16& lo) {
    hi = __float2bfloat16(v);
    lo = __float2bfloat16(v - __bfloat162float(hi));
}

__device__ __forceinline__ void mma_bf16(float* c, const unsigned* a, const unsigned* b) {
    asm volatile(
        "mma.sync.aligned.m16n8k16.row.col.f32.bf16.bf16.f32 "
        "{%0,%1,%2,%3}, {%4,%5,%6,%7}, {%8,%9}, {%0,%1,%2,%3};"
        : "+f"(c[0]), "+f"(c[1]), "+f"(c[2]), "+f"(c[3])
        : "r"(a[0]), "r"(a[1]), "r"(a[2]), "r"(a[3]), "r"(b[0]), "r"(b[1]));
}

__global__ void __launch_bounds__(256) gemm_kernel(const float* __restrict__ x,
                                                   const float* __restrict__ W) {
    __shared__ __nv_bfloat16 As_hi[128][APAD];
    __shared__ __nv_bfloat16 As_lo[128][APAD];
    __shared__ __nv_bfloat16 Bs_hi[64][APAD];
    __shared__ __nv_bfloat16 Bs_lo[64][APAD];

    const int brow = blockIdx.x * 128;
    const int bcol = blockIdx.y * 64;
    const int tid  = threadIdx.x;
    const int lane = tid & 31;
    const int wid  = tid >> 5;
    const int wm   = (wid & 1) * 64;    // warp m offset within block
    const int wn   = (wid >> 1) * 16;   // warp n offset within block
    const int qr   = lane >> 2;         // 0..7
    const int qc   = lane & 3;          // 0..3

    float acc[4][2][4];
#pragma unroll
    for (int mi = 0; mi < 4; mi++)
#pragma unroll
        for (int ni = 0; ni < 2; ni++)
#pragma unroll
            for (int r = 0; r < 4; r++) acc[mi][ni][r] = 0.0f;

    // A load assignment: row = tid>>1 (0..127), half = tid&1 -> cols half*16..+15
    const int arow  = tid >> 1;
    const int ahalf = (tid & 1) * 16;
    const bool avalid = (brow + arow < N_NODES);
    const float* xrow = x + (size_t)(brow + arow) * D + ahalf;

    for (int kb = 0; kb < D; kb += 32) {
        __syncthreads();   // previous compute done before overwrite
        // ---- A tile: 128x32 fp32 -> hi/lo bf16 ----
        {
#pragma unroll
            for (int f = 0; f < 4; f++) {
                float4 v = avalid ? *reinterpret_cast<const float4*>(xrow + kb + f * 4)
                                  : make_float4(0.f, 0.f, 0.f, 0.f);
                int c0 = ahalf + f * 4;
                __nv_bfloat16 h, l;
                bf16_split(v.x, h, l); As_hi[arow][c0 + 0] = h; As_lo[arow][c0 + 0] = l;
                bf16_split(v.y, h, l); As_hi[arow][c0 + 1] = h; As_lo[arow][c0 + 1] = l;
                bf16_split(v.z, h, l); As_hi[arow][c0 + 2] = h; As_lo[arow][c0 + 2] = l;
                bf16_split(v.w, h, l); As_hi[arow][c0 + 3] = h; As_lo[arow][c0 + 3] = l;
            }
        }
        // ---- B tile: 64x32 fp32 -> hi/lo bf16 (W rows bcol..bcol+63) ----
        {
#pragma unroll
            for (int u0 = 0; u0 < 2; u0++) {
                int u  = tid + u0 * 256;       // 0..511
                int br = u >> 3;               // 0..63
                int f  = u & 7;                // float4 index
                float4 v = *reinterpret_cast<const float4*>(
                    W + (size_t)(bcol + br) * D + kb + f * 4);
                int c0 = f * 4;
                __nv_bfloat16 h, l;
                bf16_split(v.x, h, l); Bs_hi[br][c0 + 0] = h; Bs_lo[br][c0 + 0] = l;
                bf16_split(v.y, h, l); Bs_hi[br][c0 + 1] = h; Bs_lo[br][c0 + 1] = l;
                bf16_split(v.z, h, l); Bs_hi[br][c0 + 2] = h; Bs_lo[br][c0 + 2] = l;
                bf16_split(v.w, h, l); Bs_hi[br][c0 + 3] = h; Bs_lo[br][c0 + 3] = l;
            }
        }
        __syncthreads();

        // ---- compute: two k16 steps ----
#pragma unroll
        for (int kk = 0; kk < 32; kk += 16) {
            unsigned ahi[4][4], alo[4][4];
#pragma unroll
            for (int mi = 0; mi < 4; mi++) {
                int r = wm + mi * 16 + qr;
                int c = kk + qc * 2;
                ahi[mi][0] = *reinterpret_cast<const unsigned*>(&As_hi[r][c]);
                ahi[mi][1] = *reinterpret_cast<const unsigned*>(&As_hi[r + 8][c]);
                ahi[mi][2] = *reinterpret_cast<const unsigned*>(&As_hi[r][c + 8]);
                ahi[mi][3] = *reinterpret_cast<const unsigned*>(&As_hi[r + 8][c + 8]);
                alo[mi][0] = *reinterpret_cast<const unsigned*>(&As_lo[r][c]);
                alo[mi][1] = *reinterpret_cast<const unsigned*>(&As_lo[r + 8][c]);
                alo[mi][2] = *reinterpret_cast<const unsigned*>(&As_lo[r][c + 8]);
                alo[mi][3] = *reinterpret_cast<const unsigned*>(&As_lo[r + 8][c + 8]);
            }
            unsigned bhi[2][2], blo[2][2];
#pragma unroll
            for (int ni = 0; ni < 2; ni++) {
                int r = wn + ni * 8 + qr;
                int c = kk + qc * 2;
                bhi[ni][0] = *reinterpret_cast<const unsigned*>(&Bs_hi[r][c]);
                bhi[ni][1] = *reinterpret_cast<const unsigned*>(&Bs_hi[r][c + 8]);
                blo[ni][0] = *reinterpret_cast<const unsigned*>(&Bs_lo[r][c]);
                blo[ni][1] = *reinterpret_cast<const unsigned*>(&Bs_lo[r][c + 8]);
            }
#pragma unroll
            for (int mi = 0; mi < 4; mi++)
#pragma unroll
                for (int ni = 0; ni < 2; ni++) {
                    mma_bf16(acc[mi][ni], ahi[mi], bhi[ni]);   // hi*hi
                    mma_bf16(acc[mi][ni], alo[mi], bhi[ni]);   // lo*hi
                    mma_bf16(acc[mi][ni], ahi[mi], blo[ni]);   // hi*lo
                }
        }
    }

    // ---- epilogue: scale rows by dinv, store fp32 ----
#pragma unroll
    for (int mi = 0; mi < 4; mi++) {
        int r0 = brow + wm + mi * 16 + qr;
        int r1 = r0 + 8;
        float dv0 = (r0 < N_NODES) ? g_dinv[r0] : 0.0f;
        float dv1 = (r1 < N_NODES) ? g_dinv[r1] : 0.0f;
#pragma unroll
        for (int ni = 0; ni < 2; ni++) {
            int c = bcol + wn + ni * 8 + qc * 2;
            if (r0 < N_NODES) {
                float2 v = make_float2(acc[mi][ni][0] * dv0, acc[mi][ni][1] * dv0);
                *reinterpret_cast<float2*>(g_hprime + (size_t)r0 * D + c) = v;
            }
            if (r1 < N_NODES) {
                float2 v = make_float2(acc[mi][ni][2] * dv1, acc[mi][ni][3] * dv1);
                *reinterpret_cast<float2*>(g_hprime + (size_t)r1 * D + c) = v;
            }
        }
    }
}

// ---------------- 6) gather-aggregate + fused BN column stats -------------
// agg[c] = dinv[c] * ( h'[c] + sum_{src in N(c)} h'[src] ) + bias
__device__ __forceinline__ void acc4(float4& a, const float4& b) {
    a.x += b.x; a.y += b.y; a.z += b.z; a.w += b.w;
}

__global__ void __launch_bounds__(256) aggregate_kernel(const float* __restrict__ bias) {
    __shared__ float s_sum[D];
    __shared__ float s_sq[D];
    const int tid  = threadIdx.x;
    const int lane = tid & 31;
    const int wid  = tid >> 5;
    s_sum[tid] = 0.0f;
    s_sq[tid]  = 0.0f;
    __syncthreads();

    const float4* hp4 = reinterpret_cast<const float4*>(g_hprime);
    float4*       out4 = reinterpret_cast<float4*>(g_agg);
    const float4* b4   = reinterpret_cast<const float4*>(bias);
    const float4 bb0 = b4[lane];
    const float4 bb1 = b4[lane + 32];

    float4 ts0 = make_float4(0.f, 0.f, 0.f, 0.f);
    float4 ts1 = make_float4(0.f, 0.f, 0.f, 0.f);
    float4 tq0 = make_float4(0.f, 0.f, 0.f, 0.f);
    float4 tq1 = make_float4(0.f, 0.f, 0.f, 0.f);

    const int warp0  = blockIdx.x * 8 + wid;
    const int nwarps = gridDim.x * 8;

    for (int c = warp0; c < N_NODES; c += nwarps) {
        float4 a0 = hp4[(size_t)c * 64 + lane];
        float4 a1 = hp4[(size_t)c * 64 + lane + 32];
        float4 e0 = make_float4(0.f, 0.f, 0.f, 0.f);
        float4 e1 = make_float4(0.f, 0.f, 0.f, 0.f);

        const int beg = g_off[c];
        const int end = beg + g_cnt[c];
        int e = beg;
        for (; e + 1 < end; e += 2) {
            int s0 = g_csr_src[e];
            int s1 = g_csr_src[e + 1];
            const float4* p0 = hp4 + (size_t)s0 * 64;
            const float4* p1 = hp4 + (size_t)s1 * 64;
            float4 u0 = p0[lane], u1 = p0[lane + 32];
            float4 w0 = p1[lane], w1 = p1[lane + 32];
            acc4(a0, u0); acc4(a1, u1);
            acc4(e0, w0); acc4(e1, w1);
        }
        if (e < end) {
            int s0 = g_csr_src[e];
            const float4* p0 = hp4 + (size_t)s0 * 64;
            acc4(a0, p0[lane]); acc4(a1, p0[lane + 32]);
        }
        acc4(a0, e0); acc4(a1, e1);

        const float dv = g_dinv[c];
        a0.x = fmaf(a0.x, dv, bb0.x); a0.y = fmaf(a0.y, dv, bb0.y);
        a0.z = fmaf(a0.z, dv, bb0.z); a0.w = fmaf(a0.w, dv, bb0.w);
        a1.x = fmaf(a1.x, dv, bb1.x); a1.y = fmaf(a1.y, dv, bb1.y);
        a1.z = fmaf(a1.z, dv, bb1.z); a1.w = fmaf(a1.w, dv, bb1.w);

        out4[(size_t)c * 64 + lane]      = a0;
        out4[(size_t)c * 64 + lane + 32] = a1;

        acc4(ts0, a0); acc4(ts1, a1);
        tq0.x = fmaf(a0.x, a0.x, tq0.x); tq0.y = fmaf(a0.y, a0.y, tq0.y);
        tq0.z = fmaf(a0.z, a0.z, tq0.z); tq0.w = fmaf(a0.w, a0.w, tq0.w);
        tq1.x = fmaf(a1.x, a1.x, tq1.x); tq1.y = fmaf(a1.y, a1.y, tq1.y);
        tq1.z = fmaf(a1.z, a1.z, tq1.z); tq1.w = fmaf(a1.w, a1.w, tq1.w);
    }

    const int c0 = 4 * lane;
    atomicAdd(&s_sum[c0 + 0], ts0.x); atomicAdd(&s_sum[c0 + 1], ts0.y);
    atomicAdd(&s_sum[c0 + 2], ts0.z); atomicAdd(&s_sum[c0 + 3], ts0.w);
    atomicAdd(&s_sum[128 + c0 + 0], ts1.x); atomicAdd(&s_sum[128 + c0 + 1], ts1.y);
    atomicAdd(&s_sum[128 + c0 + 2], ts1.z); atomicAdd(&s_sum[128 + c0 + 3], ts1.w);
    atomicAdd(&s_sq[c0 + 0], tq0.x); atomicAdd(&s_sq[c0 + 1], tq0.y);
    atomicAdd(&s_sq[c0 + 2], tq0.z); atomicAdd(&s_sq[c0 + 3], tq0.w);
    atomicAdd(&s_sq[128 + c0 + 0], tq1.x); atomicAdd(&s_sq[128 + c0 + 1], tq1.y);
    atomicAdd(&s_sq[128 + c0 + 2], tq1.z); atomicAdd(&s_sq[128 + c0 + 3], tq1.w);
    __syncthreads();

    atomicAdd(&g_sum[tid],   s_sum[tid]);
    atomicAdd(&g_sumsq[tid], s_sq[tid]);
}

// ---------------- 7) BN affine params ----------
__global__ void bn_params_kernel(const float* __restrict__ gamma,
                                 const float* __restrict__ beta) {
    int t = threadIdx.x;
    float invN = 1.0f / (float)N_NODES;
    float mean = g_sum[t] * invN;
    float var  = g_sumsq[t] * invN - mean * mean;
    float sc   = gamma[t] * rsqrtf(var + BN_EPS);
    g_scale[t] = sc;
    g_shift[t] = beta[t] - mean * sc;
}

// ---------------- 8) y = relu(agg*scale + shift) ----------
__global__ void output_kernel(float* __restrict__ out) {
    int i = blockIdx.x * blockDim.x + threadIdx.x;       // float4 index
    const int total4 = N_NODES * D / 4;
    if (i >= total4) return;
    int c = (i & 63) * 4;
    float4 v  = reinterpret_cast<const float4*>(g_agg)[i];
    float4 sc = *reinterpret_cast<const float4*>(g_scale + c);
    float4 sh = *reinterpret_cast<const float4*>(g_shift + c);
    float4 y;
    y.x = fmaxf(fmaf(v.x, sc.x, sh.x), 0.0f);
    y.y = fmaxf(fmaf(v.y, sc.y, sh.y), 0.0f);
    y.z = fmaxf(fmaf(v.z, sc.z, sh.z), 0.0f);
    y.w = fmaxf(fmaf(v.w, sc.w, sh.w), 0.0f);
    reinterpret_cast<float4*>(out)[i] = y;
}

// ---------------- launch ----------------
extern "C" void kernel_launch(void* const* d_in, const int* in_sizes, int n_in,
                              void* d_out, int out_size) {
    const float* x     = (const float*)d_in[0];
    const int*   ei    = (const int*)d_in[1];     // int32 (JAX x64 disabled)
    const float* W     = (const float*)d_in[2];
    const float* bias  = (const float*)d_in[3];
    const float* gamma = (const float*)d_in[4];
    const float* beta  = (const float*)d_in[5];
    const int*   row   = ei;              // sources
    const int*   col   = ei + N_EDGES;    // targets
    float* out = (float*)d_out;

    init_kernel<<<(N_NODES + 255) / 256, 256>>>();
    count_kernel<<<(N_EDGES + 255) / 256, 256>>>(col);
    blocksum_kernel<<<SCAN_NB, 256>>>();
    partscan_kernel<<<1, 256>>>();
    offsets_kernel<<<SCAN_NB, 256>>>();
    fill_kernel<<<(N_EDGES + 255) / 256, 256>>>(row, col);

    dim3 gemm_grid((N_NODES + 127) / 128, D / 64);
    gemm_kernel<<<gemm_grid, 256>>>(x, W);

    aggregate_kernel<<<592, 256>>>(bias);

    bn_params_kernel<<<1, 256>>>(gamma, beta);
    output_kernel<<<(N_NODES * D / 4 + 255) / 256, 256>>>(out);
}

// round 12
// speedup vs baseline: 2.1516x; 1.1075x over previous
#include <cuda_runtime.h>
#include <cuda_bf16.h>
#include <cstdint>

#define N_NODES 50000
#define N_EDGES 800000
#define D 256
#define BN_EPS 1e-5f
#define SCAN_NB 196            // ceil(50000/256)

// ---------------- scratch (device globals: allocation-free) ----------------
__device__ int   g_cnt[N_NODES];
__device__ int   g_fill[N_NODES];
__device__ int   g_off[N_NODES];
__device__ int   g_csr_src[N_EDGES];
__device__ float g_dinv[N_NODES];
__device__ int   g_part[256];
__device__ int   g_partpref[256];
__device__ __nv_bfloat16 g_xhi[(size_t)N_NODES * D];
__device__ __nv_bfloat16 g_xlo[(size_t)N_NODES * D];
__device__ __nv_bfloat16 g_whi[D * D];
__device__ __nv_bfloat16 g_wlo[D * D];
__device__ float g_hprime[(size_t)N_NODES * D];
__device__ float g_agg[(size_t)N_NODES * D];
__device__ float g_sum[D];
__device__ float g_sumsq[D];
__device__ float g_scale[D];
__device__ float g_shift[D];

// ---------------- 1) init counters + BN sums ----------------
__global__ void init_kernel() {
    int i = blockIdx.x * blockDim.x + threadIdx.x;
    if (i < N_NODES) { g_cnt[i] = 0; g_fill[i] = 0; }
    if (i < D) { g_sum[i] = 0.0f; g_sumsq[i] = 0.0f; }
}

// ---------------- 2) in-degree count ----------------
__global__ void count_kernel(const int* __restrict__ col) {
    int e = blockIdx.x * blockDim.x + threadIdx.x;
    if (e < N_EDGES) atomicAdd(&g_cnt[col[e]], 1);
}

// ---------------- 3a) per-block sums ----------------
__global__ void __launch_bounds__(256) blocksum_kernel() {
    const int tid  = threadIdx.x;
    const int lane = tid & 31;
    const int wid  = tid >> 5;
    int i = blockIdx.x * 256 + tid;
    int v = (i < N_NODES) ? g_cnt[i] : 0;
#pragma unroll
    for (int ofs = 16; ofs > 0; ofs >>= 1)
        v += __shfl_down_sync(0xffffffffu, v, ofs);
    __shared__ int ws[8];
    if (lane == 0) ws[wid] = v;
    __syncthreads();
    if (tid == 0) {
        int s = 0;
#pragma unroll
        for (int w = 0; w < 8; w++) s += ws[w];
        g_part[blockIdx.x] = s;
    }
}

// ---------------- 3b) scan of partials ----------------
__global__ void __launch_bounds__(256) partscan_kernel() {
    __shared__ int sm[256];
    const int tid = threadIdx.x;
    int v = (tid < SCAN_NB) ? g_part[tid] : 0;
    sm[tid] = v;
    __syncthreads();
#pragma unroll
    for (int ofs = 1; ofs < 256; ofs <<= 1) {
        int t = (tid >= ofs) ? sm[tid - ofs] : 0;
        __syncthreads();
        sm[tid] += t;
        __syncthreads();
    }
    if (tid < SCAN_NB) g_partpref[tid] = sm[tid] - v;
}

// ---------------- 3c) offsets + dinv ----------------
__global__ void __launch_bounds__(256) offsets_kernel() {
    __shared__ int sm[256];
    const int tid = threadIdx.x;
    int i = blockIdx.x * 256 + tid;
    int v = (i < N_NODES) ? g_cnt[i] : 0;
    sm[tid] = v;
    __syncthreads();
#pragma unroll
    for (int ofs = 1; ofs < 256; ofs <<= 1) {
        int t = (tid >= ofs) ? sm[tid - ofs] : 0;
        __syncthreads();
        sm[tid] += t;
        __syncthreads();
    }
    if (i < N_NODES) {
        g_off[i]  = sm[tid] - v + g_partpref[blockIdx.x];
        g_dinv[i] = rsqrtf((float)(v + 1));
    }
}

// ---------------- 4) fill CSR ----------------
__global__ void fill_kernel(const int* __restrict__ row,
                            const int* __restrict__ col) {
    int e = blockIdx.x * blockDim.x + threadIdx.x;
    if (e >= N_EDGES) return;
    int src = row[e];
    int dst = col[e];
    int pos = g_off[dst] + atomicAdd(&g_fill[dst], 1);
    g_csr_src[pos] = src;
}

// ---------------- 5a) pre-split x and W into hi/lo bf16 -------------------
__device__ __forceinline__ unsigned pack_bf2(float a, float b) {
    __nv_bfloat162 p = __floats2bfloat162_rn(a, b);
    return *reinterpret_cast<unsigned*>(&p);
}
__global__ void __launch_bounds__(256) convert_kernel(const float* __restrict__ x,
                                                      const float* __restrict__ W) {
    const int XN4 = N_NODES * D / 4;      // 3.2M
    const int WN4 = D * D / 4;            // 16384
    int i = blockIdx.x * blockDim.x + threadIdx.x;
    if (i < XN4) {
        float4 v = reinterpret_cast<const float4*>(x)[i];
        float hx = __bfloat162float(__float2bfloat16(v.x));
        float hy = __bfloat162float(__float2bfloat16(v.y));
        float hz = __bfloat162float(__float2bfloat16(v.z));
        float hw = __bfloat162float(__float2bfloat16(v.w));
        uint2 hi = make_uint2(pack_bf2(v.x, v.y), pack_bf2(v.z, v.w));
        uint2 lo = make_uint2(pack_bf2(v.x - hx, v.y - hy), pack_bf2(v.z - hz, v.w - hw));
        reinterpret_cast<uint2*>(g_xhi)[i] = hi;
        reinterpret_cast<uint2*>(g_xlo)[i] = lo;
    } else if (i < XN4 + WN4) {
        int j = i - XN4;
        float4 v = reinterpret_cast<const float4*>(W)[j];
        float hx = __bfloat162float(__float2bfloat16(v.x));
        float hy = __bfloat162float(__float2bfloat16(v.y));
        float hz = __bfloat162float(__float2bfloat16(v.z));
        float hw = __bfloat162float(__float2bfloat16(v.w));
        uint2 hi = make_uint2(pack_bf2(v.x, v.y), pack_bf2(v.z, v.w));
        uint2 lo = make_uint2(pack_bf2(v.x - hx, v.y - hy), pack_bf2(v.z - hz, v.w - hw));
        reinterpret_cast<uint2*>(g_whi)[j] = hi;
        reinterpret_cast<uint2*>(g_wlo)[j] = lo;
    }
}

// ---------------- 5b) tensor-core GEMM: h' = dinv .* (x @ W^T) ------------
// 3xBF16 split on mma.sync.m16n8k16, ldmatrix fragment loads.
// BM=128, BN=64, BK=32. 8 warps: wm = (wid&1)*64, wn = (wid>>1)*16.
#define APAD 40

__device__ __forceinline__ void mma_bf16(float* c, const unsigned* a, const unsigned* b) {
    asm volatile(
        "mma.sync.aligned.m16n8k16.row.col.f32.bf16.bf16.f32 "
        "{%0,%1,%2,%3}, {%4,%5,%6,%7}, {%8,%9}, {%0,%1,%2,%3};"
        : "+f"(c[0]), "+f"(c[1]), "+f"(c[2]), "+f"(c[3])
        : "r"(a[0]), "r"(a[1]), "r"(a[2]), "r"(a[3]), "r"(b[0]), "r"(b[1]));
}
__device__ __forceinline__ void ldmx4(unsigned* r, unsigned addr) {
    asm volatile("ldmatrix.sync.aligned.m8n8.x4.shared.b16 {%0,%1,%2,%3}, [%4];"
                 : "=r"(r[0]), "=r"(r[1]), "=r"(r[2]), "=r"(r[3]) : "r"(addr));
}
__device__ __forceinline__ void ldmx2(unsigned* r, unsigned addr) {
    asm volatile("ldmatrix.sync.aligned.m8n8.x2.shared.b16 {%0,%1}, [%2];"
                 : "=r"(r[0]), "=r"(r[1]) : "r"(addr));
}
__device__ __forceinline__ unsigned s2u(const void* p) {
    return (unsigned)__cvta_generic_to_shared(p);
}

__global__ void __launch_bounds__(256) gemm_kernel() {
    __shared__ __nv_bfloat16 As_hi[128][APAD];
    __shared__ __nv_bfloat16 As_lo[128][APAD];
    __shared__ __nv_bfloat16 Bs_hi[64][APAD];
    __shared__ __nv_bfloat16 Bs_lo[64][APAD];

    const int brow = blockIdx.x * 128;
    const int bcol = blockIdx.y * 64;
    const int tid  = threadIdx.x;
    const int lane = tid & 31;
    const int wid  = tid >> 5;
    const int wm   = (wid & 1) * 64;
    const int wn   = (wid >> 1) * 16;
    const int lr   = lane & 7;
    const int grp  = lane >> 3;          // 0..3

    float acc[4][2][4];
#pragma unroll
    for (int mi = 0; mi < 4; mi++)
#pragma unroll
        for (int ni = 0; ni < 2; ni++)
#pragma unroll
            for (int r = 0; r < 4; r++) acc[mi][ni][r] = 0.0f;

    // A staging: row = tid>>1, cols half*16..+15 (2 uint4 per array)
    const int arow   = tid >> 1;
    const int ahalf  = (tid & 1) * 16;
    const bool avalid = (brow + arow < N_NODES);
    const __nv_bfloat16* xh = g_xhi + (size_t)(brow + arow) * D + ahalf;
    const __nv_bfloat16* xl = g_xlo + (size_t)(brow + arow) * D + ahalf;
    // B staging: row = tid>>2 (0..63), chunk = tid&3 (8 cols)
    const int brr = tid >> 2;
    const int bf  = (tid & 3) * 8;
    const __nv_bfloat16* wh = g_whi + (size_t)(bcol + brr) * D + bf;
    const __nv_bfloat16* wl = g_wlo + (size_t)(bcol + brr) * D + bf;

    uint4 sah0, sah1, sal0, sal1, sbh, sbl;
    const uint4 z4 = make_uint4(0, 0, 0, 0);

    // prefetch kb=0
    {
        sah0 = avalid ? *reinterpret_cast<const uint4*>(xh)     : z4;
        sah1 = avalid ? *reinterpret_cast<const uint4*>(xh + 8) : z4;
        sal0 = avalid ? *reinterpret_cast<const uint4*>(xl)     : z4;
        sal1 = avalid ? *reinterpret_cast<const uint4*>(xl + 8) : z4;
        sbh  = *reinterpret_cast<const uint4*>(wh);
        sbl  = *reinterpret_cast<const uint4*>(wl);
    }

    for (int kb = 0; kb < D; kb += 32) {
        // commit staged tile to smem
        *reinterpret_cast<uint4*>(&As_hi[arow][ahalf])     = sah0;
        *reinterpret_cast<uint4*>(&As_hi[arow][ahalf + 8]) = sah1;
        *reinterpret_cast<uint4*>(&As_lo[arow][ahalf])     = sal0;
        *reinterpret_cast<uint4*>(&As_lo[arow][ahalf + 8]) = sal1;
        *reinterpret_cast<uint4*>(&Bs_hi[brr][bf])         = sbh;
        *reinterpret_cast<uint4*>(&Bs_lo[brr][bf])         = sbl;
        __syncthreads();

        // prefetch next tile while computing
        if (kb + 32 < D) {
            int nk = kb + 32;
            sah0 = avalid ? *reinterpret_cast<const uint4*>(xh + nk)     : z4;
            sah1 = avalid ? *reinterpret_cast<const uint4*>(xh + nk + 8) : z4;
            sal0 = avalid ? *reinterpret_cast<const uint4*>(xl + nk)     : z4;
            sal1 = avalid ? *reinterpret_cast<const uint4*>(xl + nk + 8) : z4;
            sbh  = *reinterpret_cast<const uint4*>(wh + nk);
            sbl  = *reinterpret_cast<const uint4*>(wl + nk);
        }

#pragma unroll
        for (int kk = 0; kk < 32; kk += 16) {
            unsigned ahi[4][4], alo[4][4], bhi[2][2], blo[2][2];
            const int ar = ((grp & 1) << 3) + lr;
            const int ac = kk + ((grp >> 1) << 3);
#pragma unroll
            for (int mi = 0; mi < 4; mi++) {
                ldmx4(ahi[mi], s2u(&As_hi[wm + mi * 16 + ar][ac]));
                ldmx4(alo[mi], s2u(&As_lo[wm + mi * 16 + ar][ac]));
            }
            const int bc = kk + ((lane >> 3) & 1) * 8;
#pragma unroll
            for (int ni = 0; ni < 2; ni++) {
                ldmx2(bhi[ni], s2u(&Bs_hi[wn + ni * 8 + lr][bc]));
                ldmx2(blo[ni], s2u(&Bs_lo[wn + ni * 8 + lr][bc]));
            }
#pragma unroll
            for (int mi = 0; mi < 4; mi++)
#pragma unroll
                for (int ni = 0; ni < 2; ni++) {
                    mma_bf16(acc[mi][ni], ahi[mi], bhi[ni]);
                    mma_bf16(acc[mi][ni], alo[mi], bhi[ni]);
                    mma_bf16(acc[mi][ni], ahi[mi], blo[ni]);
                }
        }
        __syncthreads();
    }

    // epilogue: scale rows by dinv, store fp32
    const int qr = lane >> 2;
    const int qc = lane & 3;
#pragma unroll
    for (int mi = 0; mi < 4; mi++) {
        int r0 = brow + wm + mi * 16 + qr;
        int r1 = r0 + 8;
        float dv0 = (r0 < N_NODES) ? g_dinv[r0] : 0.0f;
        float dv1 = (r1 < N_NODES) ? g_dinv[r1] : 0.0f;
#pragma unroll
        for (int ni = 0; ni < 2; ni++) {
            int c = bcol + wn + ni * 8 + qc * 2;
            if (r0 < N_NODES) {
                float2 v = make_float2(acc[mi][ni][0] * dv0, acc[mi][ni][1] * dv0);
                *reinterpret_cast<float2*>(g_hprime + (size_t)r0 * D + c) = v;
            }
            if (r1 < N_NODES) {
                float2 v = make_float2(acc[mi][ni][2] * dv1, acc[mi][ni][3] * dv1);
                *reinterpret_cast<float2*>(g_hprime + (size_t)r1 * D + c) = v;
            }
        }
    }
}

// ---------------- 6) gather-aggregate + fused BN column stats -------------
__device__ __forceinline__ void acc4(float4& a, const float4& b) {
    a.x += b.x; a.y += b.y; a.z += b.z; a.w += b.w;
}

__global__ void __launch_bounds__(256) aggregate_kernel(const float* __restrict__ bias) {
    __shared__ float s_sum[D];
    __shared__ float s_sq[D];
    const int tid  = threadIdx.x;
    const int lane = tid & 31;
    const int wid  = tid >> 5;
    s_sum[tid] = 0.0f;
    s_sq[tid]  = 0.0f;
    __syncthreads();

    const float4* hp4 = reinterpret_cast<const float4*>(g_hprime);
    float4*       out4 = reinterpret_cast<float4*>(g_agg);
    const float4* b4   = reinterpret_cast<const float4*>(bias);
    const float4 bb0 = b4[lane];
    const float4 bb1 = b4[lane + 32];

    float4 ts0 = make_float4(0.f, 0.f, 0.f, 0.f);
    float4 ts1 = make_float4(0.f, 0.f, 0.f, 0.f);
    float4 tq0 = make_float4(0.f, 0.f, 0.f, 0.f);
    float4 tq1 = make_float4(0.f, 0.f, 0.f, 0.f);

    const int warp0  = blockIdx.x * 8 + wid;
    const int nwarps = gridDim.x * 8;

    for (int c = warp0; c < N_NODES; c += nwarps) {
        float4 a0 = hp4[(size_t)c * 64 + lane];
        float4 a1 = hp4[(size_t)c * 64 + lane + 32];
        float4 e0 = make_float4(0.f, 0.f, 0.f, 0.f);
        float4 e1 = make_float4(0.f, 0.f, 0.f, 0.f);

        const int beg = g_off[c];
        const int end = beg + g_cnt[c];
        int e = beg;
        for (; e + 1 < end; e += 2) {
            int s0 = g_csr_src[e];
            int s1 = g_csr_src[e + 1];
            const float4* p0 = hp4 + (size_t)s0 * 64;
            const float4* p1 = hp4 + (size_t)s1 * 64;
            float4 u0 = p0[lane], u1 = p0[lane + 32];
            float4 w0 = p1[lane], w1 = p1[lane + 32];
            acc4(a0, u0); acc4(a1, u1);
            acc4(e0, w0); acc4(e1, w1);
        }
        if (e < end) {
            int s0 = g_csr_src[e];
            const float4* p0 = hp4 + (size_t)s0 * 64;
            acc4(a0, p0[lane]); acc4(a1, p0[lane + 32]);
        }
        acc4(a0, e0); acc4(a1, e1);

        const float dv = g_dinv[c];
        a0.x = fmaf(a0.x, dv, bb0.x); a0.y = fmaf(a0.y, dv, bb0.y);
        a0.z = fmaf(a0.z, dv, bb0.z); a0.w = fmaf(a0.w, dv, bb0.w);
        a1.x = fmaf(a1.x, dv, bb1.x); a1.y = fmaf(a1.y, dv, bb1.y);
        a1.z = fmaf(a1.z, dv, bb1.z); a1.w = fmaf(a1.w, dv, bb1.w);

        out4[(size_t)c * 64 + lane]      = a0;
        out4[(size_t)c * 64 + lane + 32] = a1;

        acc4(ts0, a0); acc4(ts1, a1);
        tq0.x = fmaf(a0.x, a0.x, tq0.x); tq0.y = fmaf(a0.y, a0.y, tq0.y);
        tq0.z = fmaf(a0.z, a0.z, tq0.z); tq0.w = fmaf(a0.w, a0.w, tq0.w);
        tq1.x = fmaf(a1.x, a1.x, tq1.x); tq1.y = fmaf(a1.y, a1.y, tq1.y);
        tq1.z = fmaf(a1.z, a1.z, tq1.z); tq1.w = fmaf(a1.w, a1.w, tq1.w);
    }

    const int c0 = 4 * lane;
    atomicAdd(&s_sum[c0 + 0], ts0.x); atomicAdd(&s_sum[c0 + 1], ts0.y);
    atomicAdd(&s_sum[c0 + 2], ts0.z); atomicAdd(&s_sum[c0 + 3], ts0.w);
    atomicAdd(&s_sum[128 + c0 + 0], ts1.x); atomicAdd(&s_sum[128 + c0 + 1], ts1.y);
    atomicAdd(&s_sum[128 + c0 + 2], ts1.z); atomicAdd(&s_sum[128 + c0 + 3], ts1.w);
    atomicAdd(&s_sq[c0 + 0], tq0.x); atomicAdd(&s_sq[c0 + 1], tq0.y);
    atomicAdd(&s_sq[c0 + 2], tq0.z); atomicAdd(&s_sq[c0 + 3], tq0.w);
    atomicAdd(&s_sq[128 + c0 + 0], tq1.x); atomicAdd(&s_sq[128 + c0 + 1], tq1.y);
    atomicAdd(&s_sq[128 + c0 + 2], tq1.z); atomicAdd(&s_sq[128 + c0 + 3], tq1.w);
    __syncthreads();

    atomicAdd(&g_sum[tid],   s_sum[tid]);
    atomicAdd(&g_sumsq[tid], s_sq[tid]);
}

// ---------------- 7) BN affine params ----------
__global__ void bn_params_kernel(const float* __restrict__ gamma,
                                 const float* __restrict__ beta) {
    int t = threadIdx.x;
    float invN = 1.0f / (float)N_NODES;
    float mean = g_sum[t] * invN;
    float var  = g_sumsq[t] * invN - mean * mean;
    float sc   = gamma[t] * rsqrtf(var + BN_EPS);
    g_scale[t] = sc;
    g_shift[t] = beta[t] - mean * sc;
}

// ---------------- 8) y = relu(agg*scale + shift) ----------
__global__ void output_kernel(float* __restrict__ out) {
    int i = blockIdx.x * blockDim.x + threadIdx.x;
    const int total4 = N_NODES * D / 4;
    if (i >= total4) return;
    int c = (i & 63) * 4;
    float4 v  = reinterpret_cast<const float4*>(g_agg)[i];
    float4 sc = *reinterpret_cast<const float4*>(g_scale + c);
    float4 sh = *reinterpret_cast<const float4*>(g_shift + c);
    float4 y;
    y.x = fmaxf(fmaf(v.x, sc.x, sh.x), 0.0f);
    y.y = fmaxf(fmaf(v.y, sc.y, sh.y), 0.0f);
    y.z = fmaxf(fmaf(v.z, sc.z, sh.z), 0.0f);
    y.w = fmaxf(fmaf(v.w, sc.w, sh.w), 0.0f);
    reinterpret_cast<float4*>(out)[i] = y;
}

// ---------------- launch ----------------
extern "C" void kernel_launch(void* const* d_in, const int* in_sizes, int n_in,
                              void* d_out, int out_size) {
    const float* x     = (const float*)d_in[0];
    const int*   ei    = (const int*)d_in[1];     // int32 (JAX x64 disabled)
    const float* W     = (const float*)d_in[2];
    const float* bias  = (const float*)d_in[3];
    const float* gamma = (const float*)d_in[4];
    const float* beta  = (const float*)d_in[5];
    const int*   row   = ei;
    const int*   col   = ei + N_EDGES;
    float* out = (float*)d_out;

    init_kernel<<<(N_NODES + 255) / 256, 256>>>();
    count_kernel<<<(N_EDGES + 255) / 256, 256>>>(col);
    blocksum_kernel<<<SCAN_NB, 256>>>();
    partscan_kernel<<<1, 256>>>();
    offsets_kernel<<<SCAN_NB, 256>>>();
    fill_kernel<<<(N_EDGES + 255) / 256, 256>>>(row, col);

    const int CONV4 = (N_NODES * D + D * D) / 4;
    convert_kernel<<<(CONV4 + 255) / 256, 256>>>(x, W);

    dim3 gemm_grid((N_NODES + 127) / 128, D / 64);
    gemm_kernel<<<gemm_grid, 256>>>();

    aggregate_kernel<<<592, 256>>>(bias);

    bn_params_kernel<<<1, 256>>>(gamma, beta);
    output_kernel<<<(N_NODES * D / 4 + 255) / 256, 256>>>(out);
}

// round 13
// speedup vs baseline: 2.4750x; 1.1503x over previous
#include <cuda_runtime.h>
#include <cuda_bf16.h>
#include <cstdint>

#define N_NODES 50000
#define N_EDGES 800000
#define D 256
#define BN_EPS 1e-5f
#define SCAN_NB 196            // ceil(50000/256)

// ---------------- scratch (device globals: allocation-free) ----------------
__device__ int   g_cnt[N_NODES];
__device__ int   g_fill[N_NODES];
__device__ int   g_off[N_NODES];
__device__ int   g_csr_src[N_EDGES];
__device__ float g_dinv[N_NODES];
__device__ int   g_part[256];
__device__ int   g_partpref[256];
__device__ __nv_bfloat16 g_whi[D * D];
__device__ __nv_bfloat16 g_wlo[D * D];
__device__ float g_hprime[(size_t)N_NODES * D];
__device__ float g_agg[(size_t)N_NODES * D];
__device__ float g_sum[D];
__device__ float g_sumsq[D];

__device__ __forceinline__ unsigned pack_bf2(float a, float b) {
    __nv_bfloat162 p = __floats2bfloat162_rn(a, b);
    return *reinterpret_cast<unsigned*>(&p);
}

// ---------------- 1) init counters + BN sums + W hi/lo split --------------
__global__ void init_kernel(const float* __restrict__ W) {
    int i = blockIdx.x * blockDim.x + threadIdx.x;
    if (i < N_NODES) { g_cnt[i] = 0; g_fill[i] = 0; }
    if (i < D) { g_sum[i] = 0.0f; g_sumsq[i] = 0.0f; }
    if (i < D * D / 4) {
        float4 v = reinterpret_cast<const float4*>(W)[i];
        float hx = __bfloat162float(__float2bfloat16(v.x));
        float hy = __bfloat162float(__float2bfloat16(v.y));
        float hz = __bfloat162float(__float2bfloat16(v.z));
        float hw = __bfloat162float(__float2bfloat16(v.w));
        uint2 hi = make_uint2(pack_bf2(v.x, v.y), pack_bf2(v.z, v.w));
        uint2 lo = make_uint2(pack_bf2(v.x - hx, v.y - hy), pack_bf2(v.z - hz, v.w - hw));
        reinterpret_cast<uint2*>(g_whi)[i] = hi;
        reinterpret_cast<uint2*>(g_wlo)[i] = lo;
    }
}

// ---------------- 2) in-degree count ----------------
__global__ void count_kernel(const int* __restrict__ col) {
    int e = blockIdx.x * blockDim.x + threadIdx.x;
    if (e < N_EDGES) atomicAdd(&g_cnt[col[e]], 1);
}

// ---------------- 3a) per-block sums ----------------
__global__ void __launch_bounds__(256) blocksum_kernel() {
    const int tid  = threadIdx.x;
    const int lane = tid & 31;
    const int wid  = tid >> 5;
    int i = blockIdx.x * 256 + tid;
    int v = (i < N_NODES) ? g_cnt[i] : 0;
#pragma unroll
    for (int ofs = 16; ofs > 0; ofs >>= 1)
        v += __shfl_down_sync(0xffffffffu, v, ofs);
    __shared__ int ws[8];
    if (lane == 0) ws[wid] = v;
    __syncthreads();
    if (tid == 0) {
        int s = 0;
#pragma unroll
        for (int w = 0; w < 8; w++) s += ws[w];
        g_part[blockIdx.x] = s;
    }
}

// ---------------- 3b) scan of partials ----------------
__global__ void __launch_bounds__(256) partscan_kernel() {
    __shared__ int sm[256];
    const int tid = threadIdx.x;
    int v = (tid < SCAN_NB) ? g_part[tid] : 0;
    sm[tid] = v;
    __syncthreads();
#pragma unroll
    for (int ofs = 1; ofs < 256; ofs <<= 1) {
        int t = (tid >= ofs) ? sm[tid - ofs] : 0;
        __syncthreads();
        sm[tid] += t;
        __syncthreads();
    }
    if (tid < SCAN_NB) g_partpref[tid] = sm[tid] - v;
}

// ---------------- 3c) offsets + dinv ----------------
__global__ void __launch_bounds__(256) offsets_kernel() {
    __shared__ int sm[256];
    const int tid = threadIdx.x;
    int i = blockIdx.x * 256 + tid;
    int v = (i < N_NODES) ? g_cnt[i] : 0;
    sm[tid] = v;
    __syncthreads();
#pragma unroll
    for (int ofs = 1; ofs < 256; ofs <<= 1) {
        int t = (tid >= ofs) ? sm[tid - ofs] : 0;
        __syncthreads();
        sm[tid] += t;
        __syncthreads();
    }
    if (i < N_NODES) {
        g_off[i]  = sm[tid] - v + g_partpref[blockIdx.x];
        g_dinv[i] = rsqrtf((float)(v + 1));
    }
}

// ---------------- 4) fill CSR ----------------
__global__ void fill_kernel(const int* __restrict__ row,
                            const int* __restrict__ col) {
    int e = blockIdx.x * blockDim.x + threadIdx.x;
    if (e >= N_EDGES) return;
    int src = row[e];
    int dst = col[e];
    int pos = g_off[dst] + atomicAdd(&g_fill[dst], 1);
    g_csr_src[pos] = src;
}

// ---------------- 5) tensor-core GEMM: h' = dinv .* (x @ W^T) -------------
// 3xBF16 split on mma.sync.m16n8k16, in-register A split, ldmatrix frags.
// BM=64, BN=128, BK=32. 8 warps: wm = (wid&1)*32, wn = (wid>>1)*32.
#define APAD 40

__device__ __forceinline__ void mma_bf16(float* c, const unsigned* a, const unsigned* b) {
    asm volatile(
        "mma.sync.aligned.m16n8k16.row.col.f32.bf16.bf16.f32 "
        "{%0,%1,%2,%3}, {%4,%5,%6,%7}, {%8,%9}, {%0,%1,%2,%3};"
        : "+f"(c[0]), "+f"(c[1]), "+f"(c[2]), "+f"(c[3])
        : "r"(a[0]), "r"(a[1]), "r"(a[2]), "r"(a[3]), "r"(b[0]), "r"(b[1]));
}
__device__ __forceinline__ void ldmx4(unsigned* r, unsigned addr) {
    asm volatile("ldmatrix.sync.aligned.m8n8.x4.shared.b16 {%0,%1,%2,%3}, [%4];"
                 : "=r"(r[0]), "=r"(r[1]), "=r"(r[2]), "=r"(r[3]) : "r"(addr));
}
__device__ __forceinline__ void ldmx2(unsigned* r, unsigned addr) {
    asm volatile("ldmatrix.sync.aligned.m8n8.x2.shared.b16 {%0,%1}, [%2];"
                 : "=r"(r[0]), "=r"(r[1]) : "r"(addr));
}
__device__ __forceinline__ unsigned s2u(const void* p) {
    return (unsigned)__cvta_generic_to_shared(p);
}
// split a float4 into packed hi / lo bf16x2 pairs
__device__ __forceinline__ void split4(float4 v, uint2& hi, uint2& lo) {
    float hx = __bfloat162float(__float2bfloat16(v.x));
    float hy = __bfloat162float(__float2bfloat16(v.y));
    float hz = __bfloat162float(__float2bfloat16(v.z));
    float hw = __bfloat162float(__float2bfloat16(v.w));
    hi = make_uint2(pack_bf2(v.x, v.y), pack_bf2(v.z, v.w));
    lo = make_uint2(pack_bf2(v.x - hx, v.y - hy), pack_bf2(v.z - hz, v.w - hw));
}

__global__ void __launch_bounds__(256) gemm_kernel(const float* __restrict__ x) {
    __shared__ __nv_bfloat16 As_hi[64][APAD];
    __shared__ __nv_bfloat16 As_lo[64][APAD];
    __shared__ __nv_bfloat16 Bs_hi[128][APAD];
    __shared__ __nv_bfloat16 Bs_lo[128][APAD];

    const int brow = blockIdx.x * 64;
    const int bcol = blockIdx.y * 128;
    const int tid  = threadIdx.x;
    const int lane = tid & 31;
    const int wid  = tid >> 5;
    const int wm   = (wid & 1) * 32;
    const int wn   = (wid >> 1) * 32;
    const int lr   = lane & 7;
    const int grp  = lane >> 3;          // 0..3

    float acc[2][4][4];
#pragma unroll
    for (int mi = 0; mi < 2; mi++)
#pragma unroll
        for (int ni = 0; ni < 4; ni++)
#pragma unroll
            for (int r = 0; r < 4; r++) acc[mi][ni][r] = 0.0f;

    // A staging: arow = tid>>2 (0..63), acol = (tid&3)*8 (two float4s)
    const int arow = tid >> 2;
    const int acol = (tid & 3) * 8;
    const bool avalid = (brow + arow < N_NODES);
    const float* xrow = x + (size_t)(brow + arow) * D + acol;
    // B staging: two uint4 per thread per array: u = tid + p*256, row=u>>2, chunk=(u&3)*8
    const int br0 = tid >> 2,          bc0 = (tid & 3) * 8;
    const int br1 = (tid + 256) >> 2,  bc1 = ((tid + 256) & 3) * 8;
    const __nv_bfloat16* wh0 = g_whi + (size_t)(bcol + br0) * D + bc0;
    const __nv_bfloat16* wl0 = g_wlo + (size_t)(bcol + br0) * D + bc0;
    const __nv_bfloat16* wh1 = g_whi + (size_t)(bcol + br1) * D + bc1;
    const __nv_bfloat16* wl1 = g_wlo + (size_t)(bcol + br1) * D + bc1;

    const float4 zf4 = make_float4(0.f, 0.f, 0.f, 0.f);
    float4 sa0, sa1;
    uint4  sbh0, sbl0, sbh1, sbl1;

    // prefetch kb = 0
    sa0  = avalid ? *reinterpret_cast<const float4*>(xrow)     : zf4;
    sa1  = avalid ? *reinterpret_cast<const float4*>(xrow + 4) : zf4;
    sbh0 = *reinterpret_cast<const uint4*>(wh0);
    sbl0 = *reinterpret_cast<const uint4*>(wl0);
    sbh1 = *reinterpret_cast<const uint4*>(wh1);
    sbl1 = *reinterpret_cast<const uint4*>(wl1);

    for (int kb = 0; kb < D; kb += 32) {
        // commit staged tile to smem (split A in registers)
        {
            uint2 h0, l0, h1, l1;
            split4(sa0, h0, l0);
            split4(sa1, h1, l1);
            *reinterpret_cast<uint4*>(&As_hi[arow][acol]) = make_uint4(h0.x, h0.y, h1.x, h1.y);
            *reinterpret_cast<uint4*>(&As_lo[arow][acol]) = make_uint4(l0.x, l0.y, l1.x, l1.y);
            *reinterpret_cast<uint4*>(&Bs_hi[br0][bc0]) = sbh0;
            *reinterpret_cast<uint4*>(&Bs_lo[br0][bc0]) = sbl0;
            *reinterpret_cast<uint4*>(&Bs_hi[br1][bc1]) = sbh1;
            *reinterpret_cast<uint4*>(&Bs_lo[br1][bc1]) = sbl1;
        }
        __syncthreads();

        // prefetch next tile
        if (kb + 32 < D) {
            int nk = kb + 32;
            sa0  = avalid ? *reinterpret_cast<const float4*>(xrow + nk)     : zf4;
            sa1  = avalid ? *reinterpret_cast<const float4*>(xrow + nk + 4) : zf4;
            sbh0 = *reinterpret_cast<const uint4*>(wh0 + nk);
            sbl0 = *reinterpret_cast<const uint4*>(wl0 + nk);
            sbh1 = *reinterpret_cast<const uint4*>(wh1 + nk);
            sbl1 = *reinterpret_cast<const uint4*>(wl1 + nk);
        }

#pragma unroll
        for (int kk = 0; kk < 32; kk += 16) {
            unsigned ahi[2][4], alo[2][4], bhi[4][2], blo[4][2];
            const int ar = ((grp & 1) << 3) + lr;
            const int ac = kk + ((grp >> 1) << 3);
#pragma unroll
            for (int mi = 0; mi < 2; mi++) {
                ldmx4(ahi[mi], s2u(&As_hi[wm + mi * 16 + ar][ac]));
                ldmx4(alo[mi], s2u(&As_lo[wm + mi * 16 + ar][ac]));
            }
            const int bc = kk + ((lane >> 3) & 1) * 8;
#pragma unroll
            for (int ni = 0; ni < 4; ni++) {
                ldmx2(bhi[ni], s2u(&Bs_hi[wn + ni * 8 + lr][bc]));
                ldmx2(blo[ni], s2u(&Bs_lo[wn + ni * 8 + lr][bc]));
            }
#pragma unroll
            for (int mi = 0; mi < 2; mi++)
#pragma unroll
                for (int ni = 0; ni < 4; ni++) {
                    mma_bf16(acc[mi][ni], ahi[mi], bhi[ni]);
                    mma_bf16(acc[mi][ni], alo[mi], bhi[ni]);
                    mma_bf16(acc[mi][ni], ahi[mi], blo[ni]);
                }
        }
        __syncthreads();
    }

    // epilogue: scale rows by dinv, store fp32
    const int qr = lane >> 2;
    const int qc = lane & 3;
#pragma unroll
    for (int mi = 0; mi < 2; mi++) {
        int r0 = brow + wm + mi * 16 + qr;
        int r1 = r0 + 8;
        float dv0 = (r0 < N_NODES) ? g_dinv[r0] : 0.0f;
        float dv1 = (r1 < N_NODES) ? g_dinv[r1] : 0.0f;
#pragma unroll
        for (int ni = 0; ni < 4; ni++) {
            int c = bcol + wn + ni * 8 + qc * 2;
            if (r0 < N_NODES) {
                float2 v = make_float2(acc[mi][ni][0] * dv0, acc[mi][ni][1] * dv0);
                *reinterpret_cast<float2*>(g_hprime + (size_t)r0 * D + c) = v;
            }
            if (r1 < N_NODES) {
                float2 v = make_float2(acc[mi][ni][2] * dv1, acc[mi][ni][3] * dv1);
                *reinterpret_cast<float2*>(g_hprime + (size_t)r1 * D + c) = v;
            }
        }
    }
}

// ---------------- 6) gather-aggregate + fused BN column stats -------------
__device__ __forceinline__ void acc4(float4& a, const float4& b) {
    a.x += b.x; a.y += b.y; a.z += b.z; a.w += b.w;
}

__global__ void __launch_bounds__(256) aggregate_kernel(const float* __restrict__ bias) {
    __shared__ float s_sum[D];
    __shared__ float s_sq[D];
    const int tid  = threadIdx.x;
    const int lane = tid & 31;
    const int wid  = tid >> 5;
    s_sum[tid] = 0.0f;
    s_sq[tid]  = 0.0f;
    __syncthreads();

    const float4* hp4 = reinterpret_cast<const float4*>(g_hprime);
    float4*       out4 = reinterpret_cast<float4*>(g_agg);
    const float4* b4   = reinterpret_cast<const float4*>(bias);
    const float4 bb0 = b4[lane];
    const float4 bb1 = b4[lane + 32];

    float4 ts0 = make_float4(0.f, 0.f, 0.f, 0.f);
    float4 ts1 = make_float4(0.f, 0.f, 0.f, 0.f);
    float4 tq0 = make_float4(0.f, 0.f, 0.f, 0.f);
    float4 tq1 = make_float4(0.f, 0.f, 0.f, 0.f);

    const int warp0  = blockIdx.x * 8 + wid;
    const int nwarps = gridDim.x * 8;

    for (int c = warp0; c < N_NODES; c += nwarps) {
        float4 a0 = hp4[(size_t)c * 64 + lane];
        float4 a1 = hp4[(size_t)c * 64 + lane + 32];
        float4 e0 = make_float4(0.f, 0.f, 0.f, 0.f);
        float4 e1 = make_float4(0.f, 0.f, 0.f, 0.f);

        const int beg = g_off[c];
        const int end = beg + g_cnt[c];
        int e = beg;
        for (; e + 1 < end; e += 2) {
            int s0 = g_csr_src[e];
            int s1 = g_csr_src[e + 1];
            const float4* p0 = hp4 + (size_t)s0 * 64;
            const float4* p1 = hp4 + (size_t)s1 * 64;
            float4 u0 = p0[lane], u1 = p0[lane + 32];
            float4 w0 = p1[lane], w1 = p1[lane + 32];
            acc4(a0, u0); acc4(a1, u1);
            acc4(e0, w0); acc4(e1, w1);
        }
        if (e < end) {
            int s0 = g_csr_src[e];
            const float4* p0 = hp4 + (size_t)s0 * 64;
            acc4(a0, p0[lane]); acc4(a1, p0[lane + 32]);
        }
        acc4(a0, e0); acc4(a1, e1);

        const float dv = g_dinv[c];
        a0.x = fmaf(a0.x, dv, bb0.x); a0.y = fmaf(a0.y, dv, bb0.y);
        a0.z = fmaf(a0.z, dv, bb0.z); a0.w = fmaf(a0.w, dv, bb0.w);
        a1.x = fmaf(a1.x, dv, bb1.x); a1.y = fmaf(a1.y, dv, bb1.y);
        a1.z = fmaf(a1.z, dv, bb1.z); a1.w = fmaf(a1.w, dv, bb1.w);

        out4[(size_t)c * 64 + lane]      = a0;
        out4[(size_t)c * 64 + lane + 32] = a1;

        acc4(ts0, a0); acc4(ts1, a1);
        tq0.x = fmaf(a0.x, a0.x, tq0.x); tq0.y = fmaf(a0.y, a0.y, tq0.y);
        tq0.z = fmaf(a0.z, a0.z, tq0.z); tq0.w = fmaf(a0.w, a0.w, tq0.w);
        tq1.x = fmaf(a1.x, a1.x, tq1.x); tq1.y = fmaf(a1.y, a1.y, tq1.y);
        tq1.z = fmaf(a1.z, a1.z, tq1.z); tq1.w = fmaf(a1.w, a1.w, tq1.w);
    }

    const int c0 = 4 * lane;
    atomicAdd(&s_sum[c0 + 0], ts0.x); atomicAdd(&s_sum[c0 + 1], ts0.y);
    atomicAdd(&s_sum[c0 + 2], ts0.z); atomicAdd(&s_sum[c0 + 3], ts0.w);
    atomicAdd(&s_sum[128 + c0 + 0], ts1.x); atomicAdd(&s_sum[128 + c0 + 1], ts1.y);
    atomicAdd(&s_sum[128 + c0 + 2], ts1.z); atomicAdd(&s_sum[128 + c0 + 3], ts1.w);
    atomicAdd(&s_sq[c0 + 0], tq0.x); atomicAdd(&s_sq[c0 + 1], tq0.y);
    atomicAdd(&s_sq[c0 + 2], tq0.z); atomicAdd(&s_sq[c0 + 3], tq0.w);
    atomicAdd(&s_sq[128 + c0 + 0], tq1.x); atomicAdd(&s_sq[128 + c0 + 1], tq1.y);
    atomicAdd(&s_sq[128 + c0 + 2], tq1.z); atomicAdd(&s_sq[128 + c0 + 3], tq1.w);
    __syncthreads();

    atomicAdd(&g_sum[tid],   s_sum[tid]);
    atomicAdd(&g_sumsq[tid], s_sq[tid]);
}

// ---------------- 7) output: y = relu(agg*scale + shift), BN params fused -
__global__ void __launch_bounds__(256) output_kernel(const float* __restrict__ gamma,
                                                     const float* __restrict__ beta,
                                                     float* __restrict__ out) {
    __shared__ float s_scale[D];
    __shared__ float s_shift[D];
    {
        int t = threadIdx.x;
        float invN = 1.0f / (float)N_NODES;
        float mean = g_sum[t] * invN;
        float var  = g_sumsq[t] * invN - mean * mean;
        float sc   = gamma[t] * rsqrtf(var + BN_EPS);
        s_scale[t] = sc;
        s_shift[t] = beta[t] - mean * sc;
    }
    __syncthreads();

    const int total4 = N_NODES * D / 4;
    int i = blockIdx.x * blockDim.x + threadIdx.x;
    if (i >= total4) return;
    int c = (i & 63) * 4;
    float4 v  = reinterpret_cast<const float4*>(g_agg)[i];
    float4 sc = *reinterpret_cast<const float4*>(s_scale + c);
    float4 sh = *reinterpret_cast<const float4*>(s_shift + c);
    float4 y;
    y.x = fmaxf(fmaf(v.x, sc.x, sh.x), 0.0f);
    y.y = fmaxf(fmaf(v.y, sc.y, sh.y), 0.0f);
    y.z = fmaxf(fmaf(v.z, sc.z, sh.z), 0.0f);
    y.w = fmaxf(fmaf(v.w, sc.w, sh.w), 0.0f);
    reinterpret_cast<float4*>(out)[i] = y;
}

// ---------------- launch ----------------
extern "C" void kernel_launch(void* const* d_in, const int* in_sizes, int n_in,
                              void* d_out, int out_size) {
    const float* x     = (const float*)d_in[0];
    const int*   ei    = (const int*)d_in[1];     // int32 (JAX x64 disabled)
    const float* W     = (const float*)d_in[2];
    const float* bias  = (const float*)d_in[3];
    const float* gamma = (const float*)d_in[4];
    const float* beta  = (const float*)d_in[5];
    const int*   row   = ei;
    const int*   col   = ei + N_EDGES;
    float* out = (float*)d_out;

    init_kernel<<<(N_NODES + 255) / 256, 256>>>(W);
    count_kernel<<<(N_EDGES + 255) / 256, 256>>>(col);
    blocksum_kernel<<<SCAN_NB, 256>>>();
    partscan_kernel<<<1, 256>>>();
    offsets_kernel<<<SCAN_NB, 256>>>();
    fill_kernel<<<(N_EDGES + 255) / 256, 256>>>(row, col);

    dim3 gemm_grid((N_NODES + 63) / 64, D / 128);
    gemm_kernel<<<gemm_grid, 256>>>(x);

    aggregate_kernel<<<592, 256>>>(bias);

    output_kernel<<<(N_NODES * D / 4 + 255) / 256, 256>>>(gamma, beta, out);
}